// round 4
// baseline (speedup 1.0000x reference)
#include <cuda_runtime.h>
#include <cuda_bf16.h>

// Sparse-row Adam (ITERATION=1, weight_decay=0).
// Inputs (metadata order):
//   d_in[0] param        float32 [500000, 128]
//   d_in[1] m            float32 [500000, 128]
//   d_in[2] v            float32 [500000, 128]
//   d_in[3] grad_values  float32 [262144, 128]
//   d_in[4] grad_indices int32   [262144]   (JAX default x64 disabled -> int32!)
// Output: concat(param_new, m_new, v_new) float32, 3 * 500000*128 elements.

#define N_ROWS 500000
#define DIM    128
#define NNZ    262144

// Compile-time Adam constants for iteration 1:
//   bc1 = 1 - 0.9   = 0.1
//   bc2 = 1 - 0.999 = 0.001
//   lr_t = 0.001 * sqrt(0.001) / 0.1
#define ONE_MINUS_B1 0.1f
#define ONE_MINUS_B2 0.001f
#define INV_BC1      10.0f
#define INV_BC2      1000.0f
#define LR_T         3.1622776601683794e-4f
#define EPS_F        1e-8f

// Inverse map: row -> grad slot (or -1). __device__ global = legal scratch.
__device__ int d_rowmap[N_ROWS];

__global__ void init_map_kernel() {
    int i = blockIdx.x * blockDim.x + threadIdx.x;
    if (i < N_ROWS) d_rowmap[i] = -1;
}

__global__ void scatter_map_kernel(const int* __restrict__ idx) {
    int i = blockIdx.x * blockDim.x + threadIdx.x;
    if (i < NNZ) d_rowmap[idx[i]] = i;
}

// One warp per row: 32 lanes x float4 = 128 floats.
// 256 threads/block -> 8 rows/block -> 62500 blocks.
__global__ void __launch_bounds__(256) adam_fused_kernel(
    const float4* __restrict__ param,
    const float4* __restrict__ m,
    const float4* __restrict__ v,
    const float4* __restrict__ grad,
    float4* __restrict__ out_p,
    float4* __restrict__ out_m,
    float4* __restrict__ out_v)
{
    const int warp_in_block = threadIdx.x >> 5;
    const int lane          = threadIdx.x & 31;
    const int row           = blockIdx.x * 8 + warp_in_block;
    if (row >= N_ROWS) return;

    const int elem = row * (DIM / 4) + lane;   // float4 index within a row

    float4 p  = param[elem];
    float4 mm = m[elem];
    float4 vv = v[elem];

    const int gslot = d_rowmap[row];           // warp-uniform broadcast load

    if (gslot >= 0) {
        const float4 g = grad[gslot * (DIM / 4) + lane];

        // m' = m + (1-b1)*(g - m)
        mm.x = fmaf(ONE_MINUS_B1, g.x - mm.x, mm.x);
        mm.y = fmaf(ONE_MINUS_B1, g.y - mm.y, mm.y);
        mm.z = fmaf(ONE_MINUS_B1, g.z - mm.z, mm.z);
        mm.w = fmaf(ONE_MINUS_B1, g.w - mm.w, mm.w);

        // v' = v + (1-b2)*(g*g - v)
        vv.x = fmaf(ONE_MINUS_B2, g.x * g.x - vv.x, vv.x);
        vv.y = fmaf(ONE_MINUS_B2, g.y * g.y - vv.y, vv.y);
        vv.z = fmaf(ONE_MINUS_B2, g.z * g.z - vv.z, vv.z);
        vv.w = fmaf(ONE_MINUS_B2, g.w * g.w - vv.w, vv.w);

        // p' = p - lr_t * (m'/bc1) / (sqrt(v'/bc2) + eps)
        p.x = p.x - LR_T * (mm.x * INV_BC1) / (sqrtf(vv.x * INV_BC2) + EPS_F);
        p.y = p.y - LR_T * (mm.y * INV_BC1) / (sqrtf(vv.y * INV_BC2) + EPS_F);
        p.z = p.z - LR_T * (mm.z * INV_BC1) / (sqrtf(vv.z * INV_BC2) + EPS_F);
        p.w = p.w - LR_T * (mm.w * INV_BC1) / (sqrtf(vv.w * INV_BC2) + EPS_F);
    }

    out_p[elem] = p;
    out_m[elem] = mm;
    out_v[elem] = vv;
}

extern "C" void kernel_launch(void* const* d_in, const int* in_sizes, int n_in,
                              void* d_out, int out_size) {
    const float4* param = (const float4*)d_in[0];
    const float4* m     = (const float4*)d_in[1];
    const float4* v     = (const float4*)d_in[2];
    const float4* grad  = (const float4*)d_in[3];
    const int*    idx   = (const int*)d_in[4];

    float* out = (float*)d_out;
    float4* out_p = (float4*)(out);
    float4* out_m = (float4*)(out + (size_t)N_ROWS * DIM);
    float4* out_v = (float4*)(out + 2 * (size_t)N_ROWS * DIM);

    init_map_kernel<<<(N_ROWS + 255) / 256, 256>>>();
    scatter_map_kernel<<<(NNZ + 255) / 256, 256>>>(idx);
    adam_fused_kernel<<<(N_ROWS + 7) / 8, 256>>>(param, m, v, grad,
                                                 out_p, out_m, out_v);
}

// round 7
// speedup vs baseline: 1.0017x; 1.0017x over previous
#include <cuda_runtime.h>
#include <cuda_bf16.h>

// Sparse-row Adam (ITERATION=1, weight_decay=0).
// Inputs (metadata order):
//   d_in[0] param        float32 [500000, 128]
//   d_in[1] m            float32 [500000, 128]
//   d_in[2] v            float32 [500000, 128]
//   d_in[3] grad_values  float32 [262144, 128]
//   d_in[4] grad_indices int32   [262144]
// Output: concat(param_new, m_new, v_new) float32, 3 * 500000*128 elements.

#define N_ROWS 500000
#define DIM    128
#define NNZ    262144

// Compile-time Adam constants for iteration 1:
//   bc1 = 1 - 0.9   = 0.1 ; bc2 = 1 - 0.999 = 0.001
//   lr_t = 0.001 * sqrt(0.001) / 0.1
#define ONE_MINUS_B1 0.1f
#define ONE_MINUS_B2 0.001f
#define INV_BC1      10.0f
#define INV_BC2      1000.0f
#define LR_T         3.1622776601683794e-4f
#define EPS_F        1e-8f

// Inverse map: row -> grad slot (or -1). __device__ global = legal scratch.
// Re-initialized each call via async memset (0xFF bytes == -1 per int).
__device__ int d_rowmap[N_ROWS];

__global__ void scatter_map_kernel(const int* __restrict__ idx) {
    int i = blockIdx.x * blockDim.x + threadIdx.x;
    if (i < NNZ) d_rowmap[idx[i]] = i;
}

// One warp per row: 32 lanes x float4 = 128 floats.
// 512 threads/block -> 16 rows/block -> 31250 blocks.
__global__ void __launch_bounds__(512) adam_fused_kernel(
    const float4* __restrict__ param,
    const float4* __restrict__ m,
    const float4* __restrict__ v,
    const float4* __restrict__ grad,
    float4* __restrict__ out_p,
    float4* __restrict__ out_m,
    float4* __restrict__ out_v)
{
    const int warp_in_block = threadIdx.x >> 5;
    const int lane          = threadIdx.x & 31;
    const int row           = blockIdx.x * 16 + warp_in_block;
    if (row >= N_ROWS) return;

    const int elem = row * (DIM / 4) + lane;   // float4 index within a row

    // Streaming loads: data is touched exactly once -> evict-first policy.
    float4 p  = __ldcs(&param[elem]);
    float4 mm = __ldcs(&m[elem]);
    float4 vv = __ldcs(&v[elem]);

    const int gslot = d_rowmap[row];           // warp-uniform broadcast load

    if (gslot >= 0) {
        const float4 g = __ldcs(&grad[gslot * (DIM / 4) + lane]);

        // m' = m + (1-b1)*(g - m)
        mm.x = fmaf(ONE_MINUS_B1, g.x - mm.x, mm.x);
        mm.y = fmaf(ONE_MINUS_B1, g.y - mm.y, mm.y);
        mm.z = fmaf(ONE_MINUS_B1, g.z - mm.z, mm.z);
        mm.w = fmaf(ONE_MINUS_B1, g.w - mm.w, mm.w);

        // v' = v + (1-b2)*(g*g - v)
        vv.x = fmaf(ONE_MINUS_B2, g.x * g.x - vv.x, vv.x);
        vv.y = fmaf(ONE_MINUS_B2, g.y * g.y - vv.y, vv.y);
        vv.z = fmaf(ONE_MINUS_B2, g.z * g.z - vv.z, vv.z);
        vv.w = fmaf(ONE_MINUS_B2, g.w * g.w - vv.w, vv.w);

        // p' = p - lr_t * (m'/bc1) / (sqrt(v'/bc2) + eps)
        p.x = p.x - LR_T * (mm.x * INV_BC1) / (sqrtf(vv.x * INV_BC2) + EPS_F);
        p.y = p.y - LR_T * (mm.y * INV_BC1) / (sqrtf(vv.y * INV_BC2) + EPS_F);
        p.z = p.z - LR_T * (mm.z * INV_BC1) / (sqrtf(vv.z * INV_BC2) + EPS_F);
        p.w = p.w - LR_T * (mm.w * INV_BC1) / (sqrtf(vv.w * INV_BC2) + EPS_F);
    }

    // Streaming stores: written once, never re-read.
    __stcs(&out_p[elem], p);
    __stcs(&out_m[elem], mm);
    __stcs(&out_v[elem], vv);
}

extern "C" void kernel_launch(void* const* d_in, const int* in_sizes, int n_in,
                              void* d_out, int out_size) {
    const float4* param = (const float4*)d_in[0];
    const float4* m     = (const float4*)d_in[1];
    const float4* v     = (const float4*)d_in[2];
    const float4* grad  = (const float4*)d_in[3];
    const int*    idx   = (const int*)d_in[4];

    float* out = (float*)d_out;
    float4* out_p = (float4*)(out);
    float4* out_m = (float4*)(out + (size_t)N_ROWS * DIM);
    float4* out_v = (float4*)(out + 2 * (size_t)N_ROWS * DIM);

    // Init map to -1 via memset node (0xFF per byte) — cheaper than a kernel.
    void* rowmap_ptr = nullptr;
    cudaGetSymbolAddress(&rowmap_ptr, d_rowmap);
    cudaMemsetAsync(rowmap_ptr, 0xFF, (size_t)N_ROWS * sizeof(int), 0);

    scatter_map_kernel<<<(NNZ + 255) / 256, 256>>>(idx);
    adam_fused_kernel<<<(N_ROWS + 15) / 16, 512>>>(param, m, v, grad,
                                                   out_p, out_m, out_v);
}

// round 8
// speedup vs baseline: 1.0075x; 1.0058x over previous
#include <cuda_runtime.h>
#include <cuda_bf16.h>

// Sparse-row Adam (ITERATION=1, weight_decay=0).
// Inputs (metadata order):
//   d_in[0] param        float32 [500000, 128]
//   d_in[1] m            float32 [500000, 128]
//   d_in[2] v            float32 [500000, 128]
//   d_in[3] grad_values  float32 [262144, 128]
//   d_in[4] grad_indices int32   [262144]
// Output: concat(param_new, m_new, v_new) float32, 3 * 500000*128 elements.

#define N_ROWS 500000
#define DIM    128
#define NNZ    262144

// Compile-time Adam constants for iteration 1:
//   bc1 = 1 - 0.9   = 0.1 ; bc2 = 1 - 0.999 = 0.001
//   lr_t = 0.001 * sqrt(0.001) / 0.1
#define ONE_MINUS_B1 0.1f
#define ONE_MINUS_B2 0.001f
#define INV_BC1      10.0f
#define INV_BC2      1000.0f
#define LR_T         3.1622776601683794e-4f
#define EPS_F        1e-8f

// Candidate map: row -> grad slot. NO init pass needed: entries are verified
// against idx[] in the main kernel (touched <=> idx[map[row]] == row).
// Zero-init at module load and identical re-scatter on every replay keep the
// result fully input-determined. Every stored value is in [0, NNZ), and the
// initial 0 is also a valid slot, so reads are always in-bounds.
__device__ int d_rowmap[N_ROWS];

// 4 indices per thread via int4 loads. NNZ % 4 == 0.
__global__ void scatter_map_kernel(const int4* __restrict__ idx) {
    int i = blockIdx.x * blockDim.x + threadIdx.x;
    if (i < NNZ / 4) {
        int4 r = idx[i];
        int base = i * 4;
        d_rowmap[r.x] = base;
        d_rowmap[r.y] = base + 1;
        d_rowmap[r.z] = base + 2;
        d_rowmap[r.w] = base + 3;
    }
}

// One warp per row: 32 lanes x float4 = 128 floats.
// 512 threads/block -> 16 rows/block -> 31250 blocks.
__global__ void __launch_bounds__(512) adam_fused_kernel(
    const float4* __restrict__ param,
    const float4* __restrict__ m,
    const float4* __restrict__ v,
    const float4* __restrict__ grad,
    const int*    __restrict__ idx,
    float4* __restrict__ out_p,
    float4* __restrict__ out_m,
    float4* __restrict__ out_v)
{
    const int warp_in_block = threadIdx.x >> 5;
    const int lane          = threadIdx.x & 31;
    const int row           = blockIdx.x * 16 + warp_in_block;
    if (row >= N_ROWS) return;

    // Issue map lookup + verification first so the (dependent) grad load can
    // start as early as possible.
    const int  gslot   = d_rowmap[row];        // warp-uniform broadcast load
    const bool touched = (idx[gslot] == row);  // verify candidate (L2-resident)

    const int elem = row * (DIM / 4) + lane;   // float4 index within a row

    // Streaming loads: data is touched exactly once -> evict-first policy.
    float4 p  = __ldcs(&param[elem]);
    float4 mm = __ldcs(&m[elem]);
    float4 vv = __ldcs(&v[elem]);

    if (touched) {
        const float4 g = __ldcs(&grad[gslot * (DIM / 4) + lane]);

        // m' = m + (1-b1)*(g - m)
        mm.x = fmaf(ONE_MINUS_B1, g.x - mm.x, mm.x);
        mm.y = fmaf(ONE_MINUS_B1, g.y - mm.y, mm.y);
        mm.z = fmaf(ONE_MINUS_B1, g.z - mm.z, mm.z);
        mm.w = fmaf(ONE_MINUS_B1, g.w - mm.w, mm.w);

        // v' = v + (1-b2)*(g*g - v)
        vv.x = fmaf(ONE_MINUS_B2, g.x * g.x - vv.x, vv.x);
        vv.y = fmaf(ONE_MINUS_B2, g.y * g.y - vv.y, vv.y);
        vv.z = fmaf(ONE_MINUS_B2, g.z * g.z - vv.z, vv.z);
        vv.w = fmaf(ONE_MINUS_B2, g.w * g.w - vv.w, vv.w);

        // p' = p - lr_t * (m'/bc1) / (sqrt(v'/bc2) + eps)
        p.x = p.x - LR_T * (mm.x * INV_BC1) / (sqrtf(vv.x * INV_BC2) + EPS_F);
        p.y = p.y - LR_T * (mm.y * INV_BC1) / (sqrtf(vv.y * INV_BC2) + EPS_F);
        p.z = p.z - LR_T * (mm.z * INV_BC1) / (sqrtf(vv.z * INV_BC2) + EPS_F);
        p.w = p.w - LR_T * (mm.w * INV_BC1) / (sqrtf(vv.w * INV_BC2) + EPS_F);
    }

    // Streaming stores: written once, never re-read.
    __stcs(&out_p[elem], p);
    __stcs(&out_m[elem], mm);
    __stcs(&out_v[elem], vv);
}

extern "C" void kernel_launch(void* const* d_in, const int* in_sizes, int n_in,
                              void* d_out, int out_size) {
    const float4* param = (const float4*)d_in[0];
    const float4* m     = (const float4*)d_in[1];
    const float4* v     = (const float4*)d_in[2];
    const float4* grad  = (const float4*)d_in[3];
    const int*    idx   = (const int*)d_in[4];

    float* out = (float*)d_out;
    float4* out_p = (float4*)(out);
    float4* out_m = (float4*)(out + (size_t)N_ROWS * DIM);
    float4* out_v = (float4*)(out + 2 * (size_t)N_ROWS * DIM);

    scatter_map_kernel<<<(NNZ / 4 + 255) / 256, 256>>>((const int4*)idx);
    adam_fused_kernel<<<(N_ROWS + 15) / 16, 512>>>(param, m, v, grad, idx,
                                                   out_p, out_m, out_v);
}